// round 14
// baseline (speedup 1.0000x reference)
#include <cuda_runtime.h>
#include <cuda_fp16.h>

// Problem constants
#define N_DRUG  10000
#define N_PROT  20000
#define DH      128
#define N_EDGES 1000000
#define N_LAB   500000
#define WMAT    (DH * DH)

// ---------------- scratch (device globals) ----------------------------------
__device__ __half g_tD[N_DRUG * DH];       // layer-1 transform (gather operand)
__device__ __half g_tP[N_PROT * DH];
__device__ __half g_tD2[N_DRUG * DH];      // layer-2 transform (avoids WAR)
__device__ __half g_tP2[N_PROT * DH];
__device__ float  g_rD[N_DRUG * DH];       // fp32 residual
__device__ float  g_rP[N_PROT * DH];
__device__ __half g_hDh[N_DRUG * DH];      // h-hi; later reused for uD
__device__ __half g_hPh[N_PROT * DH];      // h-hi; later reused for uP
__device__ __half g_xDh[N_DRUG * DH];      // z-hi (decoder A)
__device__ __half g_xPh[N_PROT * DH];
__device__ __half g_Wh[10 * WMAT];         // weight hi [k][n]
__device__ __half g_Wl[10 * WMAT];         // weight lo [k][n]

__device__ int g_cntP[N_PROT];
__device__ int g_cntD[N_DRUG];
__device__ int g_offP[N_PROT + 1];
__device__ int g_offD[N_DRUG + 1];
__device__ int g_rnkP[N_EDGES];
__device__ int g_rnkD[N_EDGES];
__device__ int g_srcP[N_EDGES];
__device__ int g_srcD[N_EDGES];

// ---------------- small helpers ---------------------------------------------
__device__ __forceinline__ unsigned smem_u32(const void* p) {
    unsigned r;
    asm("{ .reg .u64 t; cvta.to.shared.u64 t, %1; cvt.u32.u64 %0, t; }"
        : "=r"(r) : "l"(p));
    return r;
}
__device__ __forceinline__ void ldsm_x4(unsigned* r, unsigned addr) {
    asm volatile("ldmatrix.sync.aligned.m8n8.x4.shared.b16 {%0,%1,%2,%3}, [%4];"
                 : "=r"(r[0]), "=r"(r[1]), "=r"(r[2]), "=r"(r[3]) : "r"(addr));
}
__device__ __forceinline__ void ldsm_x4_t(unsigned* r, unsigned addr) {
    asm volatile("ldmatrix.sync.aligned.m8n8.x4.trans.shared.b16 {%0,%1,%2,%3}, [%4];"
                 : "=r"(r[0]), "=r"(r[1]), "=r"(r[2]), "=r"(r[3]) : "r"(addr));
}
__device__ __forceinline__ void mma16816(float* d, const unsigned* a, const unsigned* b) {
    asm volatile("mma.sync.aligned.m16n8k16.row.col.f32.f16.f16.f32 "
                 "{%0,%1,%2,%3}, {%4,%5,%6,%7}, {%8,%9}, {%0,%1,%2,%3};"
                 : "+f"(d[0]), "+f"(d[1]), "+f"(d[2]), "+f"(d[3])
                 : "r"(a[0]), "r"(a[1]), "r"(a[2]), "r"(a[3]),
                   "r"(b[0]), "r"(b[1]));
}
__device__ __forceinline__ void split_f4(float4 v, uint2& hi, uint2& lo) {
    __half2 h01 = __floats2half2_rn(v.x, v.y);
    __half2 h23 = __floats2half2_rn(v.z, v.w);
    float2 f01 = __half22float2(h01);
    float2 f23 = __half22float2(h23);
    __half2 l01 = __floats2half2_rn(v.x - f01.x, v.y - f01.y);
    __half2 l23 = __floats2half2_rn(v.z - f23.x, v.w - f23.y);
    hi.x = *(unsigned*)&h01; hi.y = *(unsigned*)&h23;
    lo.x = *(unsigned*)&l01; lo.y = *(unsigned*)&l23;
}
__device__ __forceinline__ uint2 f4_to_h4(float4 v) {
    __half2 h01 = __floats2half2_rn(v.x, v.y);
    __half2 h23 = __floats2half2_rn(v.z, v.w);
    uint2 r;
    r.x = *(unsigned*)&h01;
    r.y = *(unsigned*)&h23;
    return r;
}
__device__ __forceinline__ void cp16(unsigned dst, const void* src, int sz) {
    asm volatile("cp.async.ca.shared.global [%0], [%1], 16, %2;"
                 :: "r"(dst), "l"(src), "r"(sz));
}
__device__ __forceinline__ void cp_commit() {
    asm volatile("cp.async.commit_group;");
}
template <int N>
__device__ __forceinline__ void cp_wait() {
    asm volatile("cp.async.wait_group %0;" :: "n"(N));
}

// ---------------- CSR build ---------------------------------------------------
__global__ void zero_counts_kernel() {
    int i = blockIdx.x * blockDim.x + threadIdx.x;
    if (i < N_PROT) g_cntP[i] = 0;
    if (i < N_DRUG) g_cntD[i] = 0;
}

__global__ void hist_kernel(const int* __restrict__ ei_row,
                            const int* __restrict__ ei_col, int n) {
    int i = blockIdx.x * blockDim.x + threadIdx.x;
    if (i < n) {
        int r = ei_row[i], c = ei_col[i];
        g_rnkP[i] = atomicAdd(&g_cntP[c], 1);
        g_rnkD[i] = atomicAdd(&g_cntD[r], 1);
    }
}

__global__ void scan_kernel() {
    const int n = (blockIdx.x == 0) ? N_PROT : N_DRUG;
    const int* cnt = (blockIdx.x == 0) ? g_cntP : g_cntD;
    int* off = (blockIdx.x == 0) ? g_offP : g_offD;

    __shared__ int sums[1024];
    int tid = threadIdx.x;
    int chunk = (n + 1023) >> 10;
    int start = tid * chunk;
    int end = start + chunk; if (end > n) end = n;
    if (start > n) start = n;

    int s = 0;
    for (int i = start; i < end; i++) s += cnt[i];
    sums[tid] = s;
    __syncthreads();
    for (int d = 1; d < 1024; d <<= 1) {
        int v = (tid >= d) ? sums[tid - d] : 0;
        __syncthreads();
        sums[tid] += v;
        __syncthreads();
    }
    int prefix = tid ? sums[tid - 1] : 0;
    for (int i = start; i < end; i++) {
        off[i] = prefix;
        prefix += cnt[i];
    }
    if (tid == 1023) off[n] = sums[1023];
}

__global__ void fill_kernel(const int* __restrict__ ei_row,
                            const int* __restrict__ ei_col, int n) {
    int i = blockIdx.x * blockDim.x + threadIdx.x;
    if (i < n) {
        int r = ei_row[i], c = ei_col[i];
        g_srcP[g_offP[c] + g_rnkP[i]] = r;
        g_srcD[g_offD[r] + g_rnkD[i]] = c;
    }
}

// ---------------- prep: weights split hi/lo only ------------------------------
struct PrepSrc { const float* w[10]; };

__global__ void __launch_bounds__(256) prep_w_kernel(PrepSrc s) {
    int m = blockIdx.x >> 4;
    int i = (blockIdx.x & 15) * 256 + threadIdx.x;
    float4 v = ((const float4*)s.w[m])[i];
    uint2 hi, lo;
    split_f4(v, hi, lo);
    ((uint2*)g_Wh)[m * (WMAT / 4) + i] = hi;
    ((uint2*)g_Wl)[m * (WMAT / 4) + i] = lo;
}

// ---------------- segment-sum: half-warp rows ----------------------------------
struct AggJob {
    const uint4* t;
    const float4* r;
    const int* off;
    const int* src;
    float4* out;         // fp32 output (or null)
    uint4* oh;           // fp16 hi output (or null)
    int n;
    int relu;
};

__device__ __forceinline__ void acc8_add(float* a, uint4 v) {
    float2 p0 = __half22float2(*(__half2*)&v.x);
    float2 p1 = __half22float2(*(__half2*)&v.y);
    float2 p2 = __half22float2(*(__half2*)&v.z);
    float2 p3 = __half22float2(*(__half2*)&v.w);
    a[0] += p0.x; a[1] += p0.y; a[2] += p1.x; a[3] += p1.y;
    a[4] += p2.x; a[5] += p2.y; a[6] += p3.x; a[7] += p3.y;
}

__global__ void __launch_bounds__(256) seg_agg_kernel(AggJob j) {
    int w = blockIdx.x * 8 + (threadIdx.x >> 5);
    int lane = threadIdx.x & 31;
    if (w >= j.n) return;

    int half_id = lane >> 4;
    int hl = lane & 15;
    int s = j.off[w], e = j.off[w + 1];

    float acc[8] = {0.f, 0.f, 0.f, 0.f, 0.f, 0.f, 0.f, 0.f};

    int i = s;
    for (; i + 8 <= e; i += 8) {
        int s0 = __ldg(j.src + i + half_id);
        int s1 = __ldg(j.src + i + 2 + half_id);
        int s2 = __ldg(j.src + i + 4 + half_id);
        int s3 = __ldg(j.src + i + 6 + half_id);
        uint4 v0 = __ldg(j.t + s0 * 16 + hl);
        uint4 v1 = __ldg(j.t + s1 * 16 + hl);
        uint4 v2 = __ldg(j.t + s2 * 16 + hl);
        uint4 v3 = __ldg(j.t + s3 * 16 + hl);
        acc8_add(acc, v0);
        acc8_add(acc, v1);
        acc8_add(acc, v2);
        acc8_add(acc, v3);
    }
    for (; i + 2 <= e; i += 2) {
        int s0 = __ldg(j.src + i + half_id);
        uint4 v0 = __ldg(j.t + s0 * 16 + hl);
        acc8_add(acc, v0);
    }
    if (i < e) {
        int s0 = __ldg(j.src + i);
        uint4 v0 = __ldg(j.t + s0 * 16 + hl);
        if (half_id == 0) acc8_add(acc, v0);
    }

    #pragma unroll
    for (int q = 0; q < 8; q++)
        acc[q] += __shfl_xor_sync(0xffffffffu, acc[q], 16);

    if (half_id == 0) {
        float4 r0 = j.r[w * 32 + hl * 2];
        float4 r1 = j.r[w * 32 + hl * 2 + 1];
        float4 o0, o1;
        o0.x = acc[0] + r0.x; o0.y = acc[1] + r0.y;
        o0.z = acc[2] + r0.z; o0.w = acc[3] + r0.w;
        o1.x = acc[4] + r1.x; o1.y = acc[5] + r1.y;
        o1.z = acc[6] + r1.z; o1.w = acc[7] + r1.w;
        if (j.relu) {
            o0.x = fmaxf(o0.x, 0.f); o0.y = fmaxf(o0.y, 0.f);
            o0.z = fmaxf(o0.z, 0.f); o0.w = fmaxf(o0.w, 0.f);
            o1.x = fmaxf(o1.x, 0.f); o1.y = fmaxf(o1.y, 0.f);
            o1.z = fmaxf(o1.z, 0.f); o1.w = fmaxf(o1.w, 0.f);
        }
        if (j.out) {
            j.out[w * 32 + hl * 2] = o0;
            j.out[w * 32 + hl * 2 + 1] = o1;
        }
        if (j.oh) {
            uint2 h0 = f4_to_h4(o0);
            uint2 h1 = f4_to_h4(o1);
            j.oh[w * 16 + hl] = make_uint4(h0.x, h0.y, h1.x, h1.y);
        }
    }
}

// ---------------- 2-term HMMA GEMM (B-corrected), fp32-A option ---------------
#define BM 128
#define BN 128
#define BK 32
#define AS_H 40
#define A_ST (BM * AS_H)
#define B_ST (BK * BN)
#define GEMM_SMEM_BYTES ((2 * A_ST + 4 * B_ST) * 2)   // 53248 B

struct GemmJob {
    const __half* Ah;      // fp16 A (or null)
    const float* A32;      // fp32 A (used when non-null)
    const __half* Bh;
    const __half* Bl;
    const float* bias;
    void* C;
    int N;
    int c_half;
    int nblocks;
};
struct GemmJobs4 { GemmJob j[4]; int n; };

__global__ void __launch_bounds__(256, 2) gemm_multi_kernel(GemmJobs4 jobs) {
    extern __shared__ __align__(16) __half smh[];
    __half* sAh = smh;
    __half* sBh = sAh + 2 * A_ST;
    __half* sBl = sBh + 2 * B_ST;

    int b = blockIdx.x;
    int ji = 0, off = 0;
    while (ji < jobs.n - 1 && b >= off + jobs.j[ji].nblocks) {
        off += jobs.j[ji].nblocks;
        ji++;
    }
    GemmJob jb = jobs.j[ji];
    int m0 = (b - off) * BM;
    bool a32 = (jb.A32 != nullptr);

    int tid = threadIdx.x;
    int lane = tid & 31;
    int wid = tid >> 5;
    int m0w = (wid & 3) * 32;
    int n0w = (wid >> 2) * 64;

    float acc[2][8][4];
    #pragma unroll
    for (int mi = 0; mi < 2; mi++)
        #pragma unroll
        for (int ni = 0; ni < 8; ni++)
            #pragma unroll
            for (int q = 0; q < 4; q++) acc[mi][ni][q] = 0.f;

    auto load_tile = [&](int st, int kb) {
        #pragma unroll
        for (int l = 0; l < 2; l++) {
            int f = tid + l * 256;
            int k = f >> 4;
            int c8b = f & 15;
            int cc = c8b ^ (k & 7);
            unsigned db = smem_u32(&sBh[st * B_ST + k * BN + cc * 8]);
            cp16(db, jb.Bh + (kb + k) * 128 + c8b * 8, 16);
            unsigned dbl = smem_u32(&sBl[st * B_ST + k * BN + cc * 8]);
            cp16(dbl, jb.Bl + (kb + k) * 128 + c8b * 8, 16);
            int row = f >> 2;
            int c8 = f & 3;
            int gr = m0 + row;
            if (a32) {
                float4 v0 = make_float4(0.f, 0.f, 0.f, 0.f);
                float4 v1 = v0;
                if (gr < jb.N) {
                    const float4* ap = (const float4*)(jb.A32 + (size_t)gr * 128 + kb + c8 * 8);
                    v0 = ap[0];
                    v1 = ap[1];
                }
                uint2 h0 = f4_to_h4(v0);
                uint2 h1 = f4_to_h4(v1);
                *(uint4*)&sAh[st * A_ST + row * AS_H + c8 * 8] =
                    make_uint4(h0.x, h0.y, h1.x, h1.y);
            } else {
                int sz = (gr < jb.N) ? 16 : 0;
                int grc = (gr < jb.N) ? gr : 0;
                unsigned da = smem_u32(&sAh[st * A_ST + row * AS_H + c8 * 8]);
                cp16(da, jb.Ah + (size_t)grc * 128 + kb + c8 * 8, sz);
            }
        }
        cp_commit();
    };

    load_tile(0, 0);
    load_tile(1, BK);

    #pragma unroll
    for (int t = 0; t < 4; t++) {
        int cur = t & 1;
        if (t < 3) cp_wait<1>(); else cp_wait<0>();
        __syncthreads();

        const __half* Ahc = sAh + cur * A_ST;
        const __half* Bhc = sBh + cur * B_ST;
        const __half* Blc = sBl + cur * B_ST;

        #pragma unroll
        for (int ks = 0; ks < 2; ks++) {
            int k0 = ks * 16;
            unsigned ah[2][4];
            #pragma unroll
            for (int mi = 0; mi < 2; mi++) {
                int ao = (m0w + mi * 16 + (lane & 15)) * AS_H + k0 +
                         ((lane >> 4) & 1) * 8;
                ldsm_x4(ah[mi], smem_u32(&Ahc[ao]));
            }
            #pragma unroll
            for (int pi = 0; pi < 4; pi++) {
                int kr = k0 + (lane & 7) + ((lane >> 3) & 1) * 8;
                int nc = n0w + pi * 16 + (lane >> 4) * 8;
                int cc = (nc >> 3) ^ (kr & 7);
                unsigned bhf[4], blf[4];
                ldsm_x4_t(bhf, smem_u32(&Bhc[kr * BN + cc * 8]));
                ldsm_x4_t(blf, smem_u32(&Blc[kr * BN + cc * 8]));
                #pragma unroll
                for (int mi = 0; mi < 2; mi++)
                    #pragma unroll
                    for (int sub = 0; sub < 2; sub++)
                        mma16816(acc[mi][pi * 2 + sub], ah[mi], bhf + 2 * sub);
                #pragma unroll
                for (int mi = 0; mi < 2; mi++)
                    #pragma unroll
                    for (int sub = 0; sub < 2; sub++)
                        mma16816(acc[mi][pi * 2 + sub], ah[mi], blf + 2 * sub);
            }
        }
        __syncthreads();
        if (t < 2) load_tile(cur, (t + 2) * BK);
    }

    // epilogue
    #pragma unroll
    for (int ni = 0; ni < 8; ni++) {
        int col = n0w + ni * 8 + (lane & 3) * 2;
        float bz0 = jb.bias ? __ldg(jb.bias + col) : 0.f;
        float bz1 = jb.bias ? __ldg(jb.bias + col + 1) : 0.f;
        #pragma unroll
        for (int mi = 0; mi < 2; mi++) {
            int r0 = m0 + m0w + mi * 16 + (lane >> 2);
            int r1 = r0 + 8;
            float e0 = acc[mi][ni][0] + bz0;
            float e1 = acc[mi][ni][1] + bz1;
            float e2 = acc[mi][ni][2] + bz0;
            float e3 = acc[mi][ni][3] + bz1;
            if (jb.c_half) {
                if (r0 < jb.N) {
                    __half2 h = __floats2half2_rn(e0, e1);
                    *(__half2*)((__half*)jb.C + r0 * 128 + col) = h;
                }
                if (r1 < jb.N) {
                    __half2 h = __floats2half2_rn(e2, e3);
                    *(__half2*)((__half*)jb.C + r1 * 128 + col) = h;
                }
            } else {
                if (r0 < jb.N)
                    *(float2*)((float*)jb.C + r0 * 128 + col) = make_float2(e0, e1);
                if (r1 < jb.N)
                    *(float2*)((float*)jb.C + r1 * 128 + col) = make_float2(e2, e3);
            }
        }
    }
}

// ---------------- decoder: half-warp dual-gather ------------------------------
__global__ void __launch_bounds__(256) decoder_kernel(
    const uint4* __restrict__ uD, const uint4* __restrict__ uP,
    const int* __restrict__ el_row, const int* __restrict__ el_col,
    const float4* __restrict__ bd1, const float4* __restrict__ w2v,
    const float* __restrict__ bd2, float* __restrict__ out, int L)
{
    int w = (blockIdx.x * blockDim.x + threadIdx.x) >> 5;
    int lane = threadIdx.x & 31;
    if (w >= L) return;
    int half_id = lane >> 4;
    int hl = lane & 15;

    int node = half_id ? __ldg(el_col + w) : __ldg(el_row + w);
    const uint4* base = half_id ? uP : uD;
    uint4 v = __ldg(base + node * 16 + hl);

    float f[8];
    *(float2*)&f[0] = __half22float2(*(__half2*)&v.x);
    *(float2*)&f[2] = __half22float2(*(__half2*)&v.y);
    *(float2*)&f[4] = __half22float2(*(__half2*)&v.z);
    *(float2*)&f[6] = __half22float2(*(__half2*)&v.w);

    float g[8];
    #pragma unroll
    for (int q = 0; q < 8; q++)
        g[q] = __shfl_xor_sync(0xffffffffu, f[q], 16);

    float p = 0.f;
    if (half_id == 0) {
        float4 b0 = __ldg(bd1 + hl * 2), b1 = __ldg(bd1 + hl * 2 + 1);
        float4 w0 = __ldg(w2v + hl * 2), w1 = __ldg(w2v + hl * 2 + 1);
        float bb[8] = {b0.x, b0.y, b0.z, b0.w, b1.x, b1.y, b1.z, b1.w};
        float ww[8] = {w0.x, w0.y, w0.z, w0.w, w1.x, w1.y, w1.z, w1.w};
        #pragma unroll
        for (int q = 0; q < 8; q++) {
            float h = fmaxf(f[q] + g[q] + bb[q], 0.f);
            p += h * ww[q];
        }
    }
    #pragma unroll
    for (int o = 8; o; o >>= 1) p += __shfl_down_sync(0xffffffffu, p, o);
    if (lane == 0) out[w] = p + __ldg(bd2);
}

// ---------------- launch ------------------------------------------------------
extern "C" void kernel_launch(void* const* d_in, const int* in_sizes, int n_in,
                              void* d_out, int out_size)
{
    const float* x_drug = (const float*)d_in[0];
    const float* x_prot = (const float*)d_in[1];
    const int*   ei_row = (const int*)d_in[2];
    const int*   ei_col = (const int*)d_in[3];
    const int*   el_row = (const int*)d_in[4];
    const int*   el_col = (const int*)d_in[5];
    const float* W1f_l = (const float*)d_in[6];
    const float* b1f   = (const float*)d_in[7];
    const float* W1f_r = (const float*)d_in[8];
    const float* W1r_l = (const float*)d_in[9];
    const float* b1r   = (const float*)d_in[10];
    const float* W1r_r = (const float*)d_in[11];
    const float* W2f_l = (const float*)d_in[12];
    const float* b2f   = (const float*)d_in[13];
    const float* W2f_r = (const float*)d_in[14];
    const float* W2r_l = (const float*)d_in[15];
    const float* b2r   = (const float*)d_in[16];
    const float* W2r_r = (const float*)d_in[17];
    const float* Wd1   = (const float*)d_in[18];
    const float* bd1   = (const float*)d_in[19];
    const float* Wd2   = (const float*)d_in[20];
    const float* bd2   = (const float*)d_in[21];

    const int nE = in_sizes[2];
    const int nL = in_sizes[4];

    float* outZd = (float*)d_out;
    float* outZp = outZd + (size_t)N_DRUG * DH;
    float* outO  = outZp + (size_t)N_PROT * DH;

    __half *tD, *tP, *tD2, *tP2, *hDh, *hPh, *xDh, *xPh, *Wh, *Wl;
    float *rD, *rP;
    cudaGetSymbolAddress((void**)&tD, g_tD);
    cudaGetSymbolAddress((void**)&tP, g_tP);
    cudaGetSymbolAddress((void**)&tD2, g_tD2);
    cudaGetSymbolAddress((void**)&tP2, g_tP2);
    cudaGetSymbolAddress((void**)&rD, g_rD);
    cudaGetSymbolAddress((void**)&rP, g_rP);
    cudaGetSymbolAddress((void**)&hDh, g_hDh);
    cudaGetSymbolAddress((void**)&hPh, g_hPh);
    cudaGetSymbolAddress((void**)&xDh, g_xDh);
    cudaGetSymbolAddress((void**)&xPh, g_xPh);
    cudaGetSymbolAddress((void**)&Wh, g_Wh);
    cudaGetSymbolAddress((void**)&Wl, g_Wl);
    int *offP, *offD, *srcP, *srcD;
    cudaGetSymbolAddress((void**)&offP, g_offP);
    cudaGetSymbolAddress((void**)&offD, g_offD);
    cudaGetSymbolAddress((void**)&srcP, g_srcP);
    cudaGetSymbolAddress((void**)&srcD, g_srcD);

    const int BD = (N_DRUG + BM - 1) / BM;   // 79
    const int BP = (N_PROT + BM - 1) / BM;   // 157
    const int gAP = (N_PROT + 7) / 8;
    const int gAD = (N_DRUG + 7) / 8;

    static cudaStream_t sC = nullptr, sP = nullptr, sD = nullptr;
    static cudaEvent_t evFork, evCSR, eG1a, eG1b, eGP2, eGD2, eUp, eUd;
    if (!sC) {
        cudaFuncSetAttribute(gemm_multi_kernel,
                             cudaFuncAttributeMaxDynamicSharedMemorySize,
                             GEMM_SMEM_BYTES);
        cudaStreamCreateWithFlags(&sC, cudaStreamNonBlocking);
        cudaStreamCreateWithFlags(&sP, cudaStreamNonBlocking);
        cudaStreamCreateWithFlags(&sD, cudaStreamNonBlocking);
        cudaEventCreateWithFlags(&evFork, cudaEventDisableTiming);
        cudaEventCreateWithFlags(&evCSR, cudaEventDisableTiming);
        cudaEventCreateWithFlags(&eG1a, cudaEventDisableTiming);
        cudaEventCreateWithFlags(&eG1b, cudaEventDisableTiming);
        cudaEventCreateWithFlags(&eGP2, cudaEventDisableTiming);
        cudaEventCreateWithFlags(&eGD2, cudaEventDisableTiming);
        cudaEventCreateWithFlags(&eUp, cudaEventDisableTiming);
        cudaEventCreateWithFlags(&eUd, cudaEventDisableTiming);
    }

    // ---- fork: CSR chain on side stream ----
    cudaEventRecord(evFork, 0);
    cudaStreamWaitEvent(sC, evFork, 0);
    zero_counts_kernel<<<(N_PROT + 255) / 256, 256, 0, sC>>>();
    hist_kernel<<<(nE + 255) / 256, 256, 0, sC>>>(ei_row, ei_col, nE);
    scan_kernel<<<2, 1024, 0, sC>>>();
    fill_kernel<<<(nE + 255) / 256, 256, 0, sC>>>(ei_row, ei_col, nE);
    cudaEventRecord(evCSR, sC);

    // ---- prep: weights only (main) ----
    {
        PrepSrc ps;
        ps.w[0] = W1f_l; ps.w[1] = W1r_r; ps.w[2] = W1r_l; ps.w[3] = W1f_r;
        ps.w[4] = W2f_l; ps.w[5] = W2r_r; ps.w[6] = W2r_l; ps.w[7] = W2f_r;
        ps.w[8] = Wd1;   ps.w[9] = Wd1 + WMAT;
        prep_w_kernel<<<160, 256>>>(ps);
    }

    // ---- layer 1 GEMMs: consumer-grouped, serialized on main (fast first) ----
    {   // G1a = {tD, rP}  -> feeds agg1P
        GemmJobs4 js;
        js.j[0] = { nullptr, x_drug, Wh + 0 * WMAT, Wl + 0 * WMAT, nullptr, tD, N_DRUG, 1, BD };
        js.j[1] = { nullptr, x_prot, Wh + 3 * WMAT, Wl + 3 * WMAT, b1f,     rP, N_PROT, 0, BP };
        js.n = 2;
        gemm_multi_kernel<<<BD + BP, 256, GEMM_SMEM_BYTES>>>(js);
        cudaEventRecord(eG1a, 0);
    }
    {   // G1b = {tP, rD}  -> feeds agg1D
        GemmJobs4 js;
        js.j[0] = { nullptr, x_prot, Wh + 2 * WMAT, Wl + 2 * WMAT, nullptr, tP, N_PROT, 1, BP };
        js.j[1] = { nullptr, x_drug, Wh + 1 * WMAT, Wl + 1 * WMAT, b1r,     rD, N_DRUG, 0, BD };
        js.n = 2;
        gemm_multi_kernel<<<BD + BP, 256, GEMM_SMEM_BYTES>>>(js);
        cudaEventRecord(eG1b, 0);
    }

    // ---- P lane: agg1P -> GP2 -> agg2P -> uP ----
    cudaStreamWaitEvent(sP, eG1a, 0);
    cudaStreamWaitEvent(sP, evCSR, 0);
    {
        AggJob j = { (const uint4*)tD, (const float4*)rP, offP, srcP,
                     nullptr, (uint4*)hPh, N_PROT, 1 };
        seg_agg_kernel<<<gAP, 256, 0, sP>>>(j);
    }
    {   // GP2 = {tP2, rP} from hPh (producer-grouped; no cross-lane wait)
        GemmJobs4 js;
        js.j[0] = { hPh, nullptr, Wh + 6 * WMAT, Wl + 6 * WMAT, nullptr, tP2, N_PROT, 1, BP };
        js.j[1] = { hPh, nullptr, Wh + 7 * WMAT, Wl + 7 * WMAT, b2f,     rP,  N_PROT, 0, BP };
        js.n = 2;
        gemm_multi_kernel<<<2 * BP, 256, GEMM_SMEM_BYTES, sP>>>(js);
        cudaEventRecord(eGP2, sP);
    }

    // ---- D lane: agg1D -> GD2 -> agg2D -> uD ----
    cudaStreamWaitEvent(sD, eG1b, 0);
    cudaStreamWaitEvent(sD, evCSR, 0);
    {
        AggJob j = { (const uint4*)tP, (const float4*)rD, offD, srcD,
                     nullptr, (uint4*)hDh, N_DRUG, 1 };
        seg_agg_kernel<<<gAD, 256, 0, sD>>>(j);
    }
    {   // GD2 = {tD2, rD} from hDh
        GemmJobs4 js;
        js.j[0] = { hDh, nullptr, Wh + 4 * WMAT, Wl + 4 * WMAT, nullptr, tD2, N_DRUG, 1, BD };
        js.j[1] = { hDh, nullptr, Wh + 5 * WMAT, Wl + 5 * WMAT, b2r,     rD,  N_DRUG, 0, BD };
        js.n = 2;
        gemm_multi_kernel<<<2 * BD, 256, GEMM_SMEM_BYTES, sD>>>(js);
        cudaEventRecord(eGD2, sD);
    }

    // ---- layer 2 aggregations (single cross-lane edge each) ----
    cudaStreamWaitEvent(sP, eGD2, 0);
    {
        AggJob j = { (const uint4*)tD2, (const float4*)rP, offP, srcP,
                     (float4*)outZp, (uint4*)xPh, N_PROT, 0 };
        seg_agg_kernel<<<gAP, 256, 0, sP>>>(j);
    }
    {   // uP = xPh @ W9 -> hPh (in-lane)
        GemmJobs4 js;
        js.j[0] = { xPh, nullptr, Wh + 9 * WMAT, Wl + 9 * WMAT, nullptr, hPh, N_PROT, 1, BP };
        js.n = 1;
        gemm_multi_kernel<<<BP, 256, GEMM_SMEM_BYTES, sP>>>(js);
        cudaEventRecord(eUp, sP);
    }

    cudaStreamWaitEvent(sD, eGP2, 0);
    {
        AggJob j = { (const uint4*)tP2, (const float4*)rD, offD, srcD,
                     (float4*)outZd, (uint4*)xDh, N_DRUG, 0 };
        seg_agg_kernel<<<gAD, 256, 0, sD>>>(j);
    }
    {   // uD = xDh @ W8 -> hDh (in-lane)
        GemmJobs4 js;
        js.j[0] = { xDh, nullptr, Wh + 8 * WMAT, Wl + 8 * WMAT, nullptr, hDh, N_DRUG, 1, BD };
        js.n = 1;
        gemm_multi_kernel<<<BD, 256, GEMM_SMEM_BYTES, sD>>>(js);
        cudaEventRecord(eUd, sD);
    }

    // ---- decoder per-edge MLP (join) ----
    cudaStreamWaitEvent(0, eUp, 0);
    cudaStreamWaitEvent(0, eUd, 0);
    decoder_kernel<<<(nL * 32 + 255) / 256, 256>>>(
        (const uint4*)hDh, (const uint4*)hPh, el_row, el_col,
        (const float4*)bd1, (const float4*)Wd2, bd2, outO, nL);
}

// round 15
// speedup vs baseline: 1.0306x; 1.0306x over previous
#include <cuda_runtime.h>
#include <cuda_fp16.h>

// Problem constants
#define N_DRUG  10000
#define N_PROT  20000
#define DH      128
#define N_EDGES 1000000
#define N_LAB   500000
#define WMAT    (DH * DH)

// ---------------- scratch (device globals) ----------------------------------
__device__ __half g_tD[N_DRUG * DH];
__device__ __half g_tP[N_PROT * DH];
__device__ float  g_rD[N_DRUG * DH];
__device__ float  g_rP[N_PROT * DH];
__device__ __half g_hDh[N_DRUG * DH];      // h-hi; later reused for uD
__device__ __half g_hPh[N_PROT * DH];      // h-hi; later reused for uP
__device__ __half g_xDh[N_DRUG * DH];      // z-hi (decoder A)
__device__ __half g_xPh[N_PROT * DH];
__device__ __half g_Wh[10 * WMAT];         // weight hi [k][n]
__device__ __half g_Wl[10 * WMAT];         // weight lo [k][n]

__device__ int g_cntP[N_PROT];
__device__ int g_cntD[N_DRUG];
__device__ int g_offP[N_PROT + 1];
__device__ int g_offD[N_DRUG + 1];
__device__ int g_rnkP[N_EDGES];
__device__ int g_rnkD[N_EDGES];
__device__ int g_srcP[N_EDGES];
__device__ int g_srcD[N_EDGES];

// ---------------- small helpers ---------------------------------------------
__device__ __forceinline__ unsigned smem_u32(const void* p) {
    unsigned r;
    asm("{ .reg .u64 t; cvta.to.shared.u64 t, %1; cvt.u32.u64 %0, t; }"
        : "=r"(r) : "l"(p));
    return r;
}
__device__ __forceinline__ void ldsm_x4(unsigned* r, unsigned addr) {
    asm volatile("ldmatrix.sync.aligned.m8n8.x4.shared.b16 {%0,%1,%2,%3}, [%4];"
                 : "=r"(r[0]), "=r"(r[1]), "=r"(r[2]), "=r"(r[3]) : "r"(addr));
}
__device__ __forceinline__ void ldsm_x4_t(unsigned* r, unsigned addr) {
    asm volatile("ldmatrix.sync.aligned.m8n8.x4.trans.shared.b16 {%0,%1,%2,%3}, [%4];"
                 : "=r"(r[0]), "=r"(r[1]), "=r"(r[2]), "=r"(r[3]) : "r"(addr));
}
__device__ __forceinline__ void mma16816(float* d, const unsigned* a, const unsigned* b) {
    asm volatile("mma.sync.aligned.m16n8k16.row.col.f32.f16.f16.f32 "
                 "{%0,%1,%2,%3}, {%4,%5,%6,%7}, {%8,%9}, {%0,%1,%2,%3};"
                 : "+f"(d[0]), "+f"(d[1]), "+f"(d[2]), "+f"(d[3])
                 : "r"(a[0]), "r"(a[1]), "r"(a[2]), "r"(a[3]),
                   "r"(b[0]), "r"(b[1]));
}
__device__ __forceinline__ void split_f4(float4 v, uint2& hi, uint2& lo) {
    __half2 h01 = __floats2half2_rn(v.x, v.y);
    __half2 h23 = __floats2half2_rn(v.z, v.w);
    float2 f01 = __half22float2(h01);
    float2 f23 = __half22float2(h23);
    __half2 l01 = __floats2half2_rn(v.x - f01.x, v.y - f01.y);
    __half2 l23 = __floats2half2_rn(v.z - f23.x, v.w - f23.y);
    hi.x = *(unsigned*)&h01; hi.y = *(unsigned*)&h23;
    lo.x = *(unsigned*)&l01; lo.y = *(unsigned*)&l23;
}
__device__ __forceinline__ uint2 f4_to_h4(float4 v) {
    __half2 h01 = __floats2half2_rn(v.x, v.y);
    __half2 h23 = __floats2half2_rn(v.z, v.w);
    uint2 r;
    r.x = *(unsigned*)&h01;
    r.y = *(unsigned*)&h23;
    return r;
}
__device__ __forceinline__ void cp16(unsigned dst, const void* src, int sz) {
    asm volatile("cp.async.ca.shared.global [%0], [%1], 16, %2;"
                 :: "r"(dst), "l"(src), "r"(sz));
}
__device__ __forceinline__ void cp_commit() {
    asm volatile("cp.async.commit_group;");
}
template <int N>
__device__ __forceinline__ void cp_wait() {
    asm volatile("cp.async.wait_group %0;" :: "n"(N));
}

// ---------------- CSR build ---------------------------------------------------
__global__ void zero_counts_kernel() {
    int i = blockIdx.x * blockDim.x + threadIdx.x;
    if (i < N_PROT) g_cntP[i] = 0;
    if (i < N_DRUG) g_cntD[i] = 0;
}

__global__ void hist_kernel(const int* __restrict__ ei_row,
                            const int* __restrict__ ei_col, int n) {
    int i = blockIdx.x * blockDim.x + threadIdx.x;
    if (i < n) {
        int r = ei_row[i], c = ei_col[i];
        g_rnkP[i] = atomicAdd(&g_cntP[c], 1);
        g_rnkD[i] = atomicAdd(&g_cntD[r], 1);
    }
}

__global__ void scan_kernel() {
    const int n = (blockIdx.x == 0) ? N_PROT : N_DRUG;
    const int* cnt = (blockIdx.x == 0) ? g_cntP : g_cntD;
    int* off = (blockIdx.x == 0) ? g_offP : g_offD;

    __shared__ int sums[1024];
    int tid = threadIdx.x;
    int chunk = (n + 1023) >> 10;
    int start = tid * chunk;
    int end = start + chunk; if (end > n) end = n;
    if (start > n) start = n;

    int s = 0;
    for (int i = start; i < end; i++) s += cnt[i];
    sums[tid] = s;
    __syncthreads();
    for (int d = 1; d < 1024; d <<= 1) {
        int v = (tid >= d) ? sums[tid - d] : 0;
        __syncthreads();
        sums[tid] += v;
        __syncthreads();
    }
    int prefix = tid ? sums[tid - 1] : 0;
    for (int i = start; i < end; i++) {
        off[i] = prefix;
        prefix += cnt[i];
    }
    if (tid == 1023) off[n] = sums[1023];
}

__global__ void fill_kernel(const int* __restrict__ ei_row,
                            const int* __restrict__ ei_col, int n) {
    int i = blockIdx.x * blockDim.x + threadIdx.x;
    if (i < n) {
        int r = ei_row[i], c = ei_col[i];
        g_srcP[g_offP[c] + g_rnkP[i]] = r;
        g_srcD[g_offD[r] + g_rnkD[i]] = c;
    }
}

// ---------------- prep: weights split hi/lo only ------------------------------
struct PrepSrc { const float* w[10]; };

__global__ void __launch_bounds__(256) prep_w_kernel(PrepSrc s) {
    int m = blockIdx.x >> 4;
    int i = (blockIdx.x & 15) * 256 + threadIdx.x;
    float4 v = ((const float4*)s.w[m])[i];
    uint2 hi, lo;
    split_f4(v, hi, lo);
    ((uint2*)g_Wh)[m * (WMAT / 4) + i] = hi;
    ((uint2*)g_Wl)[m * (WMAT / 4) + i] = lo;
}

// ---------------- segment-sum: half-warp rows ----------------------------------
struct AggJob {
    const uint4* t;
    const float4* r;
    const int* off;
    const int* src;
    float4* out;         // fp32 output (or null)
    uint4* oh;           // fp16 hi output (or null)
    int n;
    int relu;
};

__device__ __forceinline__ void acc8_add(float* a, uint4 v) {
    float2 p0 = __half22float2(*(__half2*)&v.x);
    float2 p1 = __half22float2(*(__half2*)&v.y);
    float2 p2 = __half22float2(*(__half2*)&v.z);
    float2 p3 = __half22float2(*(__half2*)&v.w);
    a[0] += p0.x; a[1] += p0.y; a[2] += p1.x; a[3] += p1.y;
    a[4] += p2.x; a[5] += p2.y; a[6] += p3.x; a[7] += p3.y;
}

__global__ void __launch_bounds__(256) seg_agg_kernel(AggJob j) {
    int w = blockIdx.x * 8 + (threadIdx.x >> 5);
    int lane = threadIdx.x & 31;
    if (w >= j.n) return;

    int half_id = lane >> 4;
    int hl = lane & 15;
    int s = j.off[w], e = j.off[w + 1];

    float acc[8] = {0.f, 0.f, 0.f, 0.f, 0.f, 0.f, 0.f, 0.f};

    int i = s;
    for (; i + 8 <= e; i += 8) {
        int s0 = __ldg(j.src + i + half_id);
        int s1 = __ldg(j.src + i + 2 + half_id);
        int s2 = __ldg(j.src + i + 4 + half_id);
        int s3 = __ldg(j.src + i + 6 + half_id);
        uint4 v0 = __ldg(j.t + s0 * 16 + hl);
        uint4 v1 = __ldg(j.t + s1 * 16 + hl);
        uint4 v2 = __ldg(j.t + s2 * 16 + hl);
        uint4 v3 = __ldg(j.t + s3 * 16 + hl);
        acc8_add(acc, v0);
        acc8_add(acc, v1);
        acc8_add(acc, v2);
        acc8_add(acc, v3);
    }
    for (; i + 2 <= e; i += 2) {
        int s0 = __ldg(j.src + i + half_id);
        uint4 v0 = __ldg(j.t + s0 * 16 + hl);
        acc8_add(acc, v0);
    }
    if (i < e) {
        int s0 = __ldg(j.src + i);
        uint4 v0 = __ldg(j.t + s0 * 16 + hl);
        if (half_id == 0) acc8_add(acc, v0);
    }

    #pragma unroll
    for (int q = 0; q < 8; q++)
        acc[q] += __shfl_xor_sync(0xffffffffu, acc[q], 16);

    if (half_id == 0) {
        float4 r0 = j.r[w * 32 + hl * 2];
        float4 r1 = j.r[w * 32 + hl * 2 + 1];
        float4 o0, o1;
        o0.x = acc[0] + r0.x; o0.y = acc[1] + r0.y;
        o0.z = acc[2] + r0.z; o0.w = acc[3] + r0.w;
        o1.x = acc[4] + r1.x; o1.y = acc[5] + r1.y;
        o1.z = acc[6] + r1.z; o1.w = acc[7] + r1.w;
        if (j.relu) {
            o0.x = fmaxf(o0.x, 0.f); o0.y = fmaxf(o0.y, 0.f);
            o0.z = fmaxf(o0.z, 0.f); o0.w = fmaxf(o0.w, 0.f);
            o1.x = fmaxf(o1.x, 0.f); o1.y = fmaxf(o1.y, 0.f);
            o1.z = fmaxf(o1.z, 0.f); o1.w = fmaxf(o1.w, 0.f);
        }
        if (j.out) {
            j.out[w * 32 + hl * 2] = o0;
            j.out[w * 32 + hl * 2 + 1] = o1;
        }
        if (j.oh) {
            uint2 h0 = f4_to_h4(o0);
            uint2 h1 = f4_to_h4(o1);
            j.oh[w * 16 + hl] = make_uint4(h0.x, h0.y, h1.x, h1.y);
        }
    }
}

// ---------------- HMMA GEMM: optional B-correction (Bl nullable) --------------
// C = A@(Bh [+ Bl])(+bias); A from fp16 (cp.async) or fp32 (LDG+convert+STS)
#define BM 128
#define BN 128
#define BK 32
#define AS_H 40
#define A_ST (BM * AS_H)
#define B_ST (BK * BN)
#define GEMM_SMEM_BYTES ((2 * A_ST + 4 * B_ST) * 2)   // 53248 B

struct GemmJob {
    const __half* Ah;      // fp16 A (or null)
    const float* A32;      // fp32 A (used when non-null)
    const __half* Bh;
    const __half* Bl;      // null -> 1-term GEMM
    const float* bias;
    void* C;
    int N;
    int c_half;
    int nblocks;
};
struct GemmJobs4 { GemmJob j[4]; int n; };

__global__ void __launch_bounds__(256, 2) gemm_multi_kernel(GemmJobs4 jobs) {
    extern __shared__ __align__(16) __half smh[];
    __half* sAh = smh;
    __half* sBh = sAh + 2 * A_ST;
    __half* sBl = sBh + 2 * B_ST;

    int b = blockIdx.x;
    int ji = 0, off = 0;
    while (ji < jobs.n - 1 && b >= off + jobs.j[ji].nblocks) {
        off += jobs.j[ji].nblocks;
        ji++;
    }
    GemmJob jb = jobs.j[ji];
    int m0 = (b - off) * BM;
    bool a32 = (jb.A32 != nullptr);
    bool use_bl = (jb.Bl != nullptr);

    int tid = threadIdx.x;
    int lane = tid & 31;
    int wid = tid >> 5;
    int m0w = (wid & 3) * 32;
    int n0w = (wid >> 2) * 64;

    float acc[2][8][4];
    #pragma unroll
    for (int mi = 0; mi < 2; mi++)
        #pragma unroll
        for (int ni = 0; ni < 8; ni++)
            #pragma unroll
            for (int q = 0; q < 4; q++) acc[mi][ni][q] = 0.f;

    auto load_tile = [&](int st, int kb) {
        #pragma unroll
        for (int l = 0; l < 2; l++) {
            int f = tid + l * 256;
            int k = f >> 4;
            int c8b = f & 15;
            int cc = c8b ^ (k & 7);
            unsigned db = smem_u32(&sBh[st * B_ST + k * BN + cc * 8]);
            cp16(db, jb.Bh + (kb + k) * 128 + c8b * 8, 16);
            if (use_bl) {
                unsigned dbl = smem_u32(&sBl[st * B_ST + k * BN + cc * 8]);
                cp16(dbl, jb.Bl + (kb + k) * 128 + c8b * 8, 16);
            }
            int row = f >> 2;
            int c8 = f & 3;
            int gr = m0 + row;
            if (a32) {
                float4 v0 = make_float4(0.f, 0.f, 0.f, 0.f);
                float4 v1 = v0;
                if (gr < jb.N) {
                    const float4* ap = (const float4*)(jb.A32 + (size_t)gr * 128 + kb + c8 * 8);
                    v0 = ap[0];
                    v1 = ap[1];
                }
                uint2 h0 = f4_to_h4(v0);
                uint2 h1 = f4_to_h4(v1);
                *(uint4*)&sAh[st * A_ST + row * AS_H + c8 * 8] =
                    make_uint4(h0.x, h0.y, h1.x, h1.y);
            } else {
                int sz = (gr < jb.N) ? 16 : 0;
                int grc = (gr < jb.N) ? gr : 0;
                unsigned da = smem_u32(&sAh[st * A_ST + row * AS_H + c8 * 8]);
                cp16(da, jb.Ah + (size_t)grc * 128 + kb + c8 * 8, sz);
            }
        }
        cp_commit();
    };

    load_tile(0, 0);
    load_tile(1, BK);

    #pragma unroll
    for (int t = 0; t < 4; t++) {
        int cur = t & 1;
        if (t < 3) cp_wait<1>(); else cp_wait<0>();
        __syncthreads();

        const __half* Ahc = sAh + cur * A_ST;
        const __half* Bhc = sBh + cur * B_ST;
        const __half* Blc = sBl + cur * B_ST;

        #pragma unroll
        for (int ks = 0; ks < 2; ks++) {
            int k0 = ks * 16;
            unsigned ah[2][4];
            #pragma unroll
            for (int mi = 0; mi < 2; mi++) {
                int ao = (m0w + mi * 16 + (lane & 15)) * AS_H + k0 +
                         ((lane >> 4) & 1) * 8;
                ldsm_x4(ah[mi], smem_u32(&Ahc[ao]));
            }
            #pragma unroll
            for (int pi = 0; pi < 4; pi++) {
                int kr = k0 + (lane & 7) + ((lane >> 3) & 1) * 8;
                int nc = n0w + pi * 16 + (lane >> 4) * 8;
                int cc = (nc >> 3) ^ (kr & 7);
                unsigned bhf[4], blf[4];
                ldsm_x4_t(bhf, smem_u32(&Bhc[kr * BN + cc * 8]));
                if (use_bl)
                    ldsm_x4_t(blf, smem_u32(&Blc[kr * BN + cc * 8]));
                #pragma unroll
                for (int mi = 0; mi < 2; mi++)
                    #pragma unroll
                    for (int sub = 0; sub < 2; sub++)
                        mma16816(acc[mi][pi * 2 + sub], ah[mi], bhf + 2 * sub);
                if (use_bl) {
                    #pragma unroll
                    for (int mi = 0; mi < 2; mi++)
                        #pragma unroll
                        for (int sub = 0; sub < 2; sub++)
                            mma16816(acc[mi][pi * 2 + sub], ah[mi], blf + 2 * sub);
                }
            }
        }
        __syncthreads();
        if (t < 2) load_tile(cur, (t + 2) * BK);
    }

    // epilogue
    #pragma unroll
    for (int ni = 0; ni < 8; ni++) {
        int col = n0w + ni * 8 + (lane & 3) * 2;
        float bz0 = jb.bias ? __ldg(jb.bias + col) : 0.f;
        float bz1 = jb.bias ? __ldg(jb.bias + col + 1) : 0.f;
        #pragma unroll
        for (int mi = 0; mi < 2; mi++) {
            int r0 = m0 + m0w + mi * 16 + (lane >> 2);
            int r1 = r0 + 8;
            float e0 = acc[mi][ni][0] + bz0;
            float e1 = acc[mi][ni][1] + bz1;
            float e2 = acc[mi][ni][2] + bz0;
            float e3 = acc[mi][ni][3] + bz1;
            if (jb.c_half) {
                if (r0 < jb.N) {
                    __half2 h = __floats2half2_rn(e0, e1);
                    *(__half2*)((__half*)jb.C + r0 * 128 + col) = h;
                }
                if (r1 < jb.N) {
                    __half2 h = __floats2half2_rn(e2, e3);
                    *(__half2*)((__half*)jb.C + r1 * 128 + col) = h;
                }
            } else {
                if (r0 < jb.N)
                    *(float2*)((float*)jb.C + r0 * 128 + col) = make_float2(e0, e1);
                if (r1 < jb.N)
                    *(float2*)((float*)jb.C + r1 * 128 + col) = make_float2(e2, e3);
            }
        }
    }
}

// ---------------- decoder: half-warp dual-gather ------------------------------
__global__ void __launch_bounds__(256) decoder_kernel(
    const uint4* __restrict__ uD, const uint4* __restrict__ uP,
    const int* __restrict__ el_row, const int* __restrict__ el_col,
    const float4* __restrict__ bd1, const float4* __restrict__ w2v,
    const float* __restrict__ bd2, float* __restrict__ out, int L)
{
    int w = (blockIdx.x * blockDim.x + threadIdx.x) >> 5;
    int lane = threadIdx.x & 31;
    if (w >= L) return;
    int half_id = lane >> 4;
    int hl = lane & 15;

    int node = half_id ? __ldg(el_col + w) : __ldg(el_row + w);
    const uint4* base = half_id ? uP : uD;
    uint4 v = __ldg(base + node * 16 + hl);

    float f[8];
    *(float2*)&f[0] = __half22float2(*(__half2*)&v.x);
    *(float2*)&f[2] = __half22float2(*(__half2*)&v.y);
    *(float2*)&f[4] = __half22float2(*(__half2*)&v.z);
    *(float2*)&f[6] = __half22float2(*(__half2*)&v.w);

    float g[8];
    #pragma unroll
    for (int q = 0; q < 8; q++)
        g[q] = __shfl_xor_sync(0xffffffffu, f[q], 16);

    float p = 0.f;
    if (half_id == 0) {
        float4 b0 = __ldg(bd1 + hl * 2), b1 = __ldg(bd1 + hl * 2 + 1);
        float4 w0 = __ldg(w2v + hl * 2), w1 = __ldg(w2v + hl * 2 + 1);
        float bb[8] = {b0.x, b0.y, b0.z, b0.w, b1.x, b1.y, b1.z, b1.w};
        float ww[8] = {w0.x, w0.y, w0.z, w0.w, w1.x, w1.y, w1.z, w1.w};
        #pragma unroll
        for (int q = 0; q < 8; q++) {
            float h = fmaxf(f[q] + g[q] + bb[q], 0.f);
            p += h * ww[q];
        }
    }
    #pragma unroll
    for (int o = 8; o; o >>= 1) p += __shfl_down_sync(0xffffffffu, p, o);
    if (lane == 0) out[w] = p + __ldg(bd2);
}

// ---------------- launch ------------------------------------------------------
extern "C" void kernel_launch(void* const* d_in, const int* in_sizes, int n_in,
                              void* d_out, int out_size)
{
    const float* x_drug = (const float*)d_in[0];
    const float* x_prot = (const float*)d_in[1];
    const int*   ei_row = (const int*)d_in[2];
    const int*   ei_col = (const int*)d_in[3];
    const int*   el_row = (const int*)d_in[4];
    const int*   el_col = (const int*)d_in[5];
    const float* W1f_l = (const float*)d_in[6];
    const float* b1f   = (const float*)d_in[7];
    const float* W1f_r = (const float*)d_in[8];
    const float* W1r_l = (const float*)d_in[9];
    const float* b1r   = (const float*)d_in[10];
    const float* W1r_r = (const float*)d_in[11];
    const float* W2f_l = (const float*)d_in[12];
    const float* b2f   = (const float*)d_in[13];
    const float* W2f_r = (const float*)d_in[14];
    const float* W2r_l = (const float*)d_in[15];
    const float* b2r   = (const float*)d_in[16];
    const float* W2r_r = (const float*)d_in[17];
    const float* Wd1   = (const float*)d_in[18];
    const float* bd1   = (const float*)d_in[19];
    const float* Wd2   = (const float*)d_in[20];
    const float* bd2   = (const float*)d_in[21];

    const int nE = in_sizes[2];
    const int nL = in_sizes[4];

    float* outZd = (float*)d_out;
    float* outZp = outZd + (size_t)N_DRUG * DH;
    float* outO  = outZp + (size_t)N_PROT * DH;

    __half *tD, *tP, *hDh, *hPh, *xDh, *xPh, *Wh, *Wl;
    float *rD, *rP;
    cudaGetSymbolAddress((void**)&tD, g_tD);
    cudaGetSymbolAddress((void**)&tP, g_tP);
    cudaGetSymbolAddress((void**)&rD, g_rD);
    cudaGetSymbolAddress((void**)&rP, g_rP);
    cudaGetSymbolAddress((void**)&hDh, g_hDh);
    cudaGetSymbolAddress((void**)&hPh, g_hPh);
    cudaGetSymbolAddress((void**)&xDh, g_xDh);
    cudaGetSymbolAddress((void**)&xPh, g_xPh);
    cudaGetSymbolAddress((void**)&Wh, g_Wh);
    cudaGetSymbolAddress((void**)&Wl, g_Wl);
    int *offP, *offD, *srcP, *srcD;
    cudaGetSymbolAddress((void**)&offP, g_offP);
    cudaGetSymbolAddress((void**)&offD, g_offD);
    cudaGetSymbolAddress((void**)&srcP, g_srcP);
    cudaGetSymbolAddress((void**)&srcD, g_srcD);

    const int BD = (N_DRUG + BM - 1) / BM;   // 79
    const int BP = (N_PROT + BM - 1) / BM;   // 157
    const int gAP = (N_PROT + 7) / 8;
    const int gAD = (N_DRUG + 7) / 8;

    static cudaStream_t sC = nullptr, sP = nullptr, sD = nullptr;
    static cudaEvent_t evFork, evCSR, eG1a, eG1b, eA1P, eA1D, eG2a, eG2b, eA2P, eA2D;
    if (!sC) {
        cudaFuncSetAttribute(gemm_multi_kernel,
                             cudaFuncAttributeMaxDynamicSharedMemorySize,
                             GEMM_SMEM_BYTES);
        cudaStreamCreateWithFlags(&sC, cudaStreamNonBlocking);
        cudaStreamCreateWithFlags(&sP, cudaStreamNonBlocking);
        cudaStreamCreateWithFlags(&sD, cudaStreamNonBlocking);
        cudaEventCreateWithFlags(&evFork, cudaEventDisableTiming);
        cudaEventCreateWithFlags(&evCSR, cudaEventDisableTiming);
        cudaEventCreateWithFlags(&eG1a, cudaEventDisableTiming);
        cudaEventCreateWithFlags(&eG1b, cudaEventDisableTiming);
        cudaEventCreateWithFlags(&eA1P, cudaEventDisableTiming);
        cudaEventCreateWithFlags(&eA1D, cudaEventDisableTiming);
        cudaEventCreateWithFlags(&eG2a, cudaEventDisableTiming);
        cudaEventCreateWithFlags(&eG2b, cudaEventDisableTiming);
        cudaEventCreateWithFlags(&eA2P, cudaEventDisableTiming);
        cudaEventCreateWithFlags(&eA2D, cudaEventDisableTiming);
    }

    // ---- fork: CSR chain on side stream ----
    cudaEventRecord(evFork, 0);
    cudaStreamWaitEvent(sC, evFork, 0);
    zero_counts_kernel<<<(N_PROT + 255) / 256, 256, 0, sC>>>();
    hist_kernel<<<(nE + 255) / 256, 256, 0, sC>>>(ei_row, ei_col, nE);
    scan_kernel<<<2, 1024, 0, sC>>>();
    fill_kernel<<<(nE + 255) / 256, 256, 0, sC>>>(ei_row, ei_col, nE);
    cudaEventRecord(evCSR, sC);

    // ---- prep: weights only (main) ----
    {
        PrepSrc ps;
        ps.w[0] = W1f_l; ps.w[1] = W1r_r; ps.w[2] = W1r_l; ps.w[3] = W1f_r;
        ps.w[4] = W2f_l; ps.w[5] = W2r_r; ps.w[6] = W2r_l; ps.w[7] = W2f_r;
        ps.w[8] = Wd1;   ps.w[9] = Wd1 + WMAT;
        prep_w_kernel<<<160, 256>>>(ps);
    }

    // ---- layer 1 GEMMs: consumer-grouped, fp32 A; t-jobs 1-term ----
    {   // G1a = {tD, rP}  -> feeds agg1P
        GemmJobs4 js;
        js.j[0] = { nullptr, x_drug, Wh + 0 * WMAT, nullptr,        nullptr, tD, N_DRUG, 1, BD };
        js.j[1] = { nullptr, x_prot, Wh + 3 * WMAT, Wl + 3 * WMAT, b1f,     rP, N_PROT, 0, BP };
        js.n = 2;
        gemm_multi_kernel<<<BD + BP, 256, GEMM_SMEM_BYTES>>>(js);
        cudaEventRecord(eG1a, 0);
    }
    {   // G1b = {tP, rD}  -> feeds agg1D
        GemmJobs4 js;
        js.j[0] = { nullptr, x_prot, Wh + 2 * WMAT, nullptr,        nullptr, tP, N_PROT, 1, BP };
        js.j[1] = { nullptr, x_drug, Wh + 1 * WMAT, Wl + 1 * WMAT, b1r,     rD, N_DRUG, 0, BD };
        js.n = 2;
        gemm_multi_kernel<<<BD + BP, 256, GEMM_SMEM_BYTES>>>(js);
        cudaEventRecord(eG1b, 0);
    }

    // ---- layer 1 aggregations on per-type streams ----
    cudaStreamWaitEvent(sP, eG1a, 0);
    cudaStreamWaitEvent(sP, evCSR, 0);
    {
        AggJob j = { (const uint4*)tD, (const float4*)rP, offP, srcP,
                     nullptr, (uint4*)hPh, N_PROT, 1 };
        seg_agg_kernel<<<gAP, 256, 0, sP>>>(j);
        cudaEventRecord(eA1P, sP);
    }
    cudaStreamWaitEvent(sD, eG1b, 0);
    cudaStreamWaitEvent(sD, evCSR, 0);
    {
        AggJob j = { (const uint4*)tP, (const float4*)rD, offD, srcD,
                     nullptr, (uint4*)hDh, N_DRUG, 1 };
        seg_agg_kernel<<<gAD, 256, 0, sD>>>(j);
        cudaEventRecord(eA1D, sD);
    }

    // ---- layer 2 GEMMs: consumer-grouped (2-term, feed fp32 outputs) ----
    cudaStreamWaitEvent(0, eA1P, 0);
    cudaStreamWaitEvent(0, eA1D, 0);
    {   // G2a = {tD', rP'} -> feeds agg2P
        GemmJobs4 js;
        js.j[0] = { hDh, nullptr, Wh + 4 * WMAT, Wl + 4 * WMAT, nullptr, tD, N_DRUG, 1, BD };
        js.j[1] = { hPh, nullptr, Wh + 7 * WMAT, Wl + 7 * WMAT, b2f,     rP, N_PROT, 0, BP };
        js.n = 2;
        gemm_multi_kernel<<<BD + BP, 256, GEMM_SMEM_BYTES>>>(js);
        cudaEventRecord(eG2a, 0);
    }
    {   // G2b = {tP', rD'} -> feeds agg2D
        GemmJobs4 js;
        js.j[0] = { hPh, nullptr, Wh + 6 * WMAT, Wl + 6 * WMAT, nullptr, tP, N_PROT, 1, BP };
        js.j[1] = { hDh, nullptr, Wh + 5 * WMAT, Wl + 5 * WMAT, b2r,     rD, N_DRUG, 0, BD };
        js.n = 2;
        gemm_multi_kernel<<<BD + BP, 256, GEMM_SMEM_BYTES>>>(js);
        cudaEventRecord(eG2b, 0);
    }

    // ---- layer 2 aggregations on per-type streams -> z fp32 + z-hi ----
    cudaStreamWaitEvent(sP, eG2a, 0);
    {
        AggJob j = { (const uint4*)tD, (const float4*)rP, offP, srcP,
                     (float4*)outZp, (uint4*)xPh, N_PROT, 0 };
        seg_agg_kernel<<<gAP, 256, 0, sP>>>(j);
        cudaEventRecord(eA2P, sP);
    }
    cudaStreamWaitEvent(sD, eG2b, 0);
    {
        AggJob j = { (const uint4*)tP, (const float4*)rD, offD, srcD,
                     (float4*)outZd, (uint4*)xDh, N_DRUG, 0 };
        seg_agg_kernel<<<gAD, 256, 0, sD>>>(j);
        cudaEventRecord(eA2D, sD);
    }

    // ---- decoder node transforms (merged, 1-term; u into retired h-hi) ----
    cudaStreamWaitEvent(0, eA2P, 0);
    cudaStreamWaitEvent(0, eA2D, 0);
    {
        GemmJobs4 js;
        js.j[0] = { xDh, nullptr, Wh + 8 * WMAT, nullptr, nullptr, hDh, N_DRUG, 1, BD };
        js.j[1] = { xPh, nullptr, Wh + 9 * WMAT, nullptr, nullptr, hPh, N_PROT, 1, BP };
        js.n = 2;
        gemm_multi_kernel<<<BD + BP, 256, GEMM_SMEM_BYTES>>>(js);
    }

    // ---- decoder per-edge MLP ----
    decoder_kernel<<<(nL * 32 + 255) / 256, 256>>>(
        (const uint4*)hDh, (const uint4*)hPh, el_row, el_col,
        (const float4*)bd1, (const float4*)Wd2, bd2, outO, nL);
}